// round 1
// baseline (speedup 1.0000x reference)
#include <cuda_runtime.h>
#include <cstdint>
#include <cstddef>

// Problem constants
#define M_TOK 65536      // 16 * 4096 tokens
#define C_DIM 512
#define NQKV  1536
#define HEADS 8
#define HD    64
#define WIN   64
#define NWIN  1024       // M_TOK / WIN

typedef unsigned long long ull;

// Scratch (allocation-free rule: __device__ globals)
__device__ float g_qkv[(size_t)M_TOK * NQKV];      // 402 MB: [token, 3*512] = q|k|v per head
__device__ float g_attnout[(size_t)M_TOK * C_DIM]; // 134 MB: attention output, heads concatenated

// ---------------- packed f32x2 helpers (Blackwell dual-FP32 pipe) ----------------
__device__ __forceinline__ ull pack2(float lo, float hi) {
    ull r; asm("mov.b64 %0, {%1,%2};" : "=l"(r) : "f"(lo), "f"(hi)); return r;
}
__device__ __forceinline__ void unpack2(ull v, float& lo, float& hi) {
    asm("mov.b64 {%0,%1}, %2;" : "=f"(lo), "=f"(hi) : "l"(v));
}
__device__ __forceinline__ void fma2(ull& c, ull a, ull b) {
    asm("fma.rn.f32x2 %0, %1, %2, %0;" : "+l"(c) : "l"(a), "l"(b));
}

// ---------------- tiled SGEMM: C[M,N] = A[M,K] @ B[K,N] (+bias), row-major ----------------
// BM=128, BN=128, BK=16, 256 threads, 8x8 per thread via 4x f32x2 accumulators.
template<bool BIAS>
__global__ __launch_bounds__(256, 2) void sgemm_kernel(
    const float* __restrict__ A, const float* __restrict__ B,
    const float* __restrict__ bias, float* __restrict__ C,
    int M, int N, int K)
{
    __shared__ float As[16][128];   // transposed A tile: As[k][m]
    __shared__ float Bs[16][128];   // Bs[k][n]

    const int tid = threadIdx.x;
    const int bm = blockIdx.y * 128;
    const int bn = blockIdx.x * 128;
    const int tx = tid & 15;   // n-direction (16 threads * 8 cols)
    const int ty = tid >> 4;   // m-direction (16 threads * 8 rows)

    const int arow = tid >> 2;          // 0..63
    const int acol = (tid & 3) << 2;    // 0,4,8,12
    const int brow = tid >> 5;          // 0..7
    const int bcol = (tid & 31) << 2;   // 0..124

    const float* Ap = A + (size_t)bm * K;
    const float* Bp = B + bn;

    ull acc[8][4];
#pragma unroll
    for (int i = 0; i < 8; i++)
#pragma unroll
        for (int j = 0; j < 4; j++) acc[i][j] = 0ULL;

    for (int k0 = 0; k0 < K; k0 += 16) {
#pragma unroll
        for (int r = 0; r < 2; r++) {
            int row = arow + r * 64;
            float4 v = *(const float4*)(Ap + (size_t)row * K + k0 + acol);
            As[acol + 0][row] = v.x;
            As[acol + 1][row] = v.y;
            As[acol + 2][row] = v.z;
            As[acol + 3][row] = v.w;
        }
#pragma unroll
        for (int r = 0; r < 2; r++) {
            int row = brow + r * 8;
            float4 v = *(const float4*)(Bp + (size_t)(k0 + row) * N + bcol);
            *(float4*)&Bs[row][bcol] = v;
        }
        __syncthreads();

#pragma unroll
        for (int kk = 0; kk < 16; kk++) {
            float4 a0 = *(const float4*)&As[kk][ty * 8];
            float4 a1 = *(const float4*)&As[kk][ty * 8 + 4];
            ull b2[4];
#pragma unroll
            for (int j = 0; j < 4; j++) b2[j] = *(const ull*)&Bs[kk][tx * 8 + 2 * j];
            float af[8] = {a0.x, a0.y, a0.z, a0.w, a1.x, a1.y, a1.z, a1.w};
#pragma unroll
            for (int i = 0; i < 8; i++) {
                ull a2 = pack2(af[i], af[i]);
#pragma unroll
                for (int j = 0; j < 4; j++) fma2(acc[i][j], a2, b2[j]);
            }
        }
        __syncthreads();
    }

#pragma unroll
    for (int i = 0; i < 8; i++) {
        float* Crow = C + (size_t)(bm + ty * 8 + i) * N + bn + tx * 8;
#pragma unroll
        for (int j = 0; j < 4; j += 2) {
            float4 v;
            unpack2(acc[i][j],     v.x, v.y);
            unpack2(acc[i][j + 1], v.z, v.w);
            if (BIAS) {
                const float* bp = bias + bn + tx * 8 + 2 * j;
                v.x += bp[0]; v.y += bp[1]; v.z += bp[2]; v.w += bp[3];
            }
            *(float4*)(Crow + 2 * j) = v;
        }
    }
}

// ---------------- fused windowed attention with double softmax ----------------
// One CTA per (window, head). 64 threads: thread t owns query row t.
// Loads K,V tiles [64,64] to smem (broadcast reads => pitch-64 is conflict-free),
// keeps its own Q row and score vector in registers, fully unrolled f32x2 math.
__global__ __launch_bounds__(64) void attn_kernel(
    const float* __restrict__ qkv, float* __restrict__ attnout)
{
    __shared__ float ks[64][64];
    __shared__ float vs[64][64];

    const int w = blockIdx.x;     // window
    const int h = blockIdx.y;     // head
    const int t = threadIdx.x;    // query row in window

    const float* base = qkv + (size_t)w * WIN * NQKV;

    // cooperative K/V tile load: 64 rows x 16 float4 each
#pragma unroll
    for (int it = 0; it < 16; it++) {
        int f = t + 64 * it;
        int row = f >> 4;
        int c4 = (f & 15) << 2;
        float4 kv = *(const float4*)(base + (size_t)row * NQKV + 512 + h * HD + c4);
        *(float4*)&ks[row][c4] = kv;
        float4 vv = *(const float4*)(base + (size_t)row * NQKV + 1024 + h * HD + c4);
        *(float4*)&vs[row][c4] = vv;
    }

    // Q row into registers (packed pairs)
    ull q2[32];
    {
        const float* qrow = base + (size_t)t * NQKV + h * HD;
#pragma unroll
        for (int i = 0; i < 16; i++) {
            float4 v = *(const float4*)(qrow + 4 * i);
            q2[2 * i]     = pack2(v.x, v.y);
            q2[2 * i + 1] = pack2(v.z, v.w);
        }
    }
    __syncthreads();

    // scores: s[j] = (q . k_j) * scale   (compute all j; mask afterwards)
    float s[64];
#pragma unroll
    for (int j = 0; j < 64; j++) {
        ull acc = 0ULL;
#pragma unroll
        for (int d = 0; d < 32; d++) {
            ull k2 = *(const ull*)&ks[j][2 * d];
            fma2(acc, q2[d], k2);
        }
        float lo, hi; unpack2(acc, lo, hi);
        s[j] = (lo + hi) * 0.125f;  // scale = 64^-0.5
    }

    // softmax #1 restricted to j <= t; masked entries -> exact 0
    float m = -1e30f;
#pragma unroll
    for (int j = 0; j < 64; j++) if (j <= t) m = fmaxf(m, s[j]);
    float z = 0.f;
#pragma unroll
    for (int j = 0; j < 64; j++) {
        float e = (j <= t) ? __expf(s[j] - m) : 0.f;
        s[j] = e;
        z += e;
    }
    const float invz = 1.f / z;

    // softmax #2 over the FULL axis (masked entries contribute exp(0)=1)
    float z2 = 0.f;
#pragma unroll
    for (int j = 0; j < 64; j++) {
        float e2 = __expf(s[j] * invz);   // probs in [0,1] => no overflow, shift-free
        s[j] = e2;
        z2 += e2;
    }
    const float invz2 = 1.f / z2;

    // out = p2 @ V   (all 64 rows of V participate)
    ull o2[32];
#pragma unroll
    for (int d = 0; d < 32; d++) o2[d] = 0ULL;
#pragma unroll
    for (int j = 0; j < 64; j++) {
        float p = s[j] * invz2;
        ull pp = pack2(p, p);
#pragma unroll
        for (int d = 0; d < 32; d++) {
            ull v2 = *(const ull*)&vs[j][2 * d];
            fma2(o2[d], pp, v2);
        }
    }

    float* orow = attnout + ((size_t)(w * WIN + t)) * C_DIM + h * HD;
#pragma unroll
    for (int d = 0; d < 16; d++) {
        float4 v;
        unpack2(o2[2 * d],     v.x, v.y);
        unpack2(o2[2 * d + 1], v.z, v.w);
        *(float4*)(orow + 4 * d) = v;
    }
}

// ---------------- launch ----------------
extern "C" void kernel_launch(void* const* d_in, const int* in_sizes, int n_in,
                              void* d_out, int out_size)
{
    const float* x     = (const float*)d_in[0];   // [16,4096,512]
    const float* Wqkv  = (const float*)d_in[1];   // [512,1536]
    const float* Wproj = (const float*)d_in[2];   // [512,512]
    const float* bproj = (const float*)d_in[3];   // [512]
    float* out = (float*)d_out;                   // [16,4096,512]

    float* qkv = nullptr;
    float* attnout = nullptr;
    cudaGetSymbolAddress((void**)&qkv, g_qkv);
    cudaGetSymbolAddress((void**)&attnout, g_attnout);

    // 1) QKV projection: [65536,512] @ [512,1536]
    sgemm_kernel<false><<<dim3(NQKV / 128, M_TOK / 128), 256>>>(
        x, Wqkv, nullptr, qkv, M_TOK, NQKV, C_DIM);

    // 2) windowed attention with double softmax
    attn_kernel<<<dim3(NWIN, HEADS), 64>>>(qkv, attnout);

    // 3) output projection + bias: [65536,512] @ [512,512]
    sgemm_kernel<true><<<dim3(C_DIM / 128, M_TOK / 128), 256>>>(
        attnout, Wproj, bproj, out, M_TOK, C_DIM, C_DIM);
}

// round 4
// speedup vs baseline: 2.1545x; 2.1545x over previous
#include <cuda_runtime.h>
#include <cstdint>
#include <cstddef>

// Problem constants
#define M_TOK 65536
#define C_DIM 512
#define NQKV  1536
#define HEADS 8
#define HD    64
#define WIN   64
#define NWIN  1024

typedef unsigned long long ull;

// ---------------- scratch ----------------
__device__ float g_xr[(size_t)M_TOK * C_DIM];       // tf32-rounded, k-permuted x
__device__ float g_qkv[(size_t)M_TOK * NQKV];       // qkv projection output
__device__ float g_attnout[(size_t)M_TOK * C_DIM];  // attention out (tf32-rounded, k-permuted)
__device__ float g_wqkvT[(size_t)NQKV * C_DIM];     // Wqkv^T, rounded+permuted
__device__ float g_wprojT[(size_t)C_DIM * C_DIM];   // Wproj^T, rounded+permuted

// ---------------- helpers ----------------
__device__ __forceinline__ float tf32r(float x) {
    uint32_t y; asm("cvt.rna.tf32.f32 %0, %1;" : "=r"(y) : "f"(x));
    return __uint_as_float(y);
}
__device__ __forceinline__ ull pack2(float lo, float hi) {
    ull r; asm("mov.b64 %0, {%1,%2};" : "=l"(r) : "f"(lo), "f"(hi)); return r;
}
__device__ __forceinline__ void unpack2(ull v, float& lo, float& hi) {
    asm("mov.b64 {%0,%1}, %2;" : "=f"(lo), "=f"(hi) : "l"(v));
}
__device__ __forceinline__ void fma2(ull& c, ull a, ull b) {
    asm("fma.rn.f32x2 %0, %1, %2, %0;" : "+l"(c) : "l"(a), "l"(b));
}
__device__ __forceinline__ uint32_t smem_u32(const void* p) {
    uint32_t a;
    asm("{ .reg .u64 t; cvta.to.shared.u64 t, %1; cvt.u32.u64 %0, t; }" : "=r"(a) : "l"(p));
    return a;
}
__device__ __forceinline__ void cpasync16(uint32_t saddr, const void* g) {
    asm volatile("cp.async.cg.shared.global [%0], [%1], 16;" :: "r"(saddr), "l"(g));
}
template<int N> __device__ __forceinline__ void cpwait() {
    asm volatile("cp.async.wait_group %0;" :: "n"(N));
}
__device__ __forceinline__ void cpcommit() {
    asm volatile("cp.async.commit_group;" ::: "memory");
}
__device__ __forceinline__ void lds64(uint32_t& x, uint32_t& y, uint32_t addr) {
    asm volatile("ld.shared.v2.b32 {%0,%1}, [%2];" : "=r"(x), "=r"(y) : "r"(addr));
}
__device__ __forceinline__ void mma_tf32(float* c, const uint32_t* a, const uint32_t* b) {
    asm volatile(
        "mma.sync.aligned.m16n8k8.row.col.f32.tf32.tf32.f32 "
        "{%0,%1,%2,%3}, {%4,%5,%6,%7}, {%8,%9}, {%0,%1,%2,%3};"
        : "+f"(c[0]), "+f"(c[1]), "+f"(c[2]), "+f"(c[3])
        : "r"(a[0]), "r"(a[1]), "r"(a[2]), "r"(a[3]), "r"(b[0]), "r"(b[1]));
}
// permutation within 8-group: k -> [0,4,1,5,2,6,3,7] positions
__device__ __forceinline__ int pi8(int c) {
    return (c & ~7) | ((c & 3) << 1) | ((c >> 2) & 1);
}

// ================= tf32 mma.sync GEMM: C[M,N] = A[M,512] @ BT[N,512]^T =================
// A and BT must be tf32-rounded and k-permuted (pi8 within 8-groups).
// CTA tile 128x256, BK=32, 3-stage cp.async, 256 threads, warp tile 64x64.
#define BM 128
#define BN 256
#define GBK 32
#define KTOT 512
#define NSTG 3
#define A_ST 16384                   // BM*GBK*4
#define B_ST 32768                   // BN*GBK*4
#define STG_BYTES (A_ST + B_ST)      // 49152
#define GEMM_SMEM (NSTG * STG_BYTES) // 147456

template<bool BIAS>
__global__ __launch_bounds__(256, 1)
void gemm_mma_kernel(const float* __restrict__ A, const float* __restrict__ BT,
                     const float* __restrict__ bias, float* __restrict__ C, int N)
{
    extern __shared__ __align__(128) char smem[];
    const uint32_t sbase = smem_u32(smem);
    const int tid  = threadIdx.x;
    const int warp = tid >> 5;
    const int lane = tid & 31;
    const int g = lane >> 2;      // groupID
    const int t = lane & 3;       // thread-in-group
    const int wm = warp & 1;      // 0..1  (m)
    const int wn = warp >> 1;     // 0..3  (n)
    const int bm = blockIdx.y * BM;
    const int bn = blockIdx.x * BN;

    const int S = KTOT / GBK;     // 16 k-blocks

    auto load_stage = [&](int s) {
        const int slot = s % NSTG;
        const uint32_t sa = sbase + slot * STG_BYTES;
        const uint32_t sb = sa + A_ST;
        const int k0 = s * GBK;
        // A: 128 rows x 8 chunks(16B). dest plane layout [kk][row][8 floats]
#pragma unroll
        for (int it = 0; it < 4; it++) {
            int i = tid + it * 256;
            int row = i >> 3, ch = i & 7;
            cpasync16(sa + (uint32_t)((ch >> 1) * (BM * 32) + row * 32 + (ch & 1) * 16),
                      A + (size_t)(bm + row) * KTOT + k0 + ch * 4);
        }
        // B: 256 rows x 8 chunks
#pragma unroll
        for (int it = 0; it < 8; it++) {
            int i = tid + it * 256;
            int row = i >> 3, ch = i & 7;
            cpasync16(sb + (uint32_t)((ch >> 1) * (BN * 32) + row * 32 + (ch & 1) * 16),
                      BT + (size_t)(bn + row) * KTOT + k0 + ch * 4);
        }
        cpcommit();
    };

    float c[4][8][4];
#pragma unroll
    for (int i = 0; i < 4; i++)
#pragma unroll
        for (int j = 0; j < 8; j++)
#pragma unroll
            for (int r = 0; r < 4; r++) c[i][j][r] = 0.f;

    // preload
    load_stage(0); load_stage(1); load_stage(2);

    for (int s = 0; s < S; s++) {
        const int slot = s % NSTG;
        const int rem = S - 1 - s;
        if (rem >= 2) cpwait<2>();
        else if (rem == 1) cpwait<1>();
        else cpwait<0>();
        __syncthreads();

        const uint32_t sa = sbase + slot * STG_BYTES;
        const uint32_t sb = sa + A_ST;

#pragma unroll
        for (int kk = 0; kk < 4; kk++) {
            uint32_t a[4][4];
#pragma unroll
            for (int i = 0; i < 4; i++) {
                uint32_t base = sa + (uint32_t)(kk * (BM * 32) + (wm * 64 + i * 16 + g) * 32 + t * 8);
                lds64(a[i][0], a[i][2], base);         // rows g
                lds64(a[i][1], a[i][3], base + 256);   // rows g+8
            }
            uint32_t b[8][2];
#pragma unroll
            for (int j = 0; j < 8; j++) {
                uint32_t base = sb + (uint32_t)(kk * (BN * 32) + (wn * 64 + j * 8 + g) * 32 + t * 8);
                lds64(b[j][0], b[j][1], base);
            }
#pragma unroll
            for (int i = 0; i < 4; i++)
#pragma unroll
                for (int j = 0; j < 8; j++)
                    mma_tf32(c[i][j], a[i], b[j]);
        }
        __syncthreads();

        if (s + NSTG < S) load_stage(s + NSTG);
    }

    // epilogue
#pragma unroll
    for (int i = 0; i < 4; i++) {
        const int row0 = bm + wm * 64 + i * 16 + g;
#pragma unroll
        for (int j = 0; j < 8; j++) {
            const int col = bn + wn * 64 + j * 8 + 2 * t;
            float2 v0 = make_float2(c[i][j][0], c[i][j][1]);
            float2 v1 = make_float2(c[i][j][2], c[i][j][3]);
            if (BIAS) {
                float b0 = bias[col], b1 = bias[col + 1];
                v0.x += b0; v0.y += b1; v1.x += b0; v1.y += b1;
            }
            *(float2*)(C + (size_t)row0 * N + col) = v0;
            *(float2*)(C + (size_t)(row0 + 8) * N + col) = v1;
        }
    }
}

// ================= prep kernels =================
// round x to tf32 and permute k within 8-groups: out 8-block = [f0,f4,f1,f5,f2,f6,f3,f7]
__global__ void round_perm_kernel(const float* __restrict__ in, float* __restrict__ out, int n8)
{
    int i = blockIdx.x * blockDim.x + threadIdx.x;
    int stride = gridDim.x * blockDim.x;
    for (; i < n8; i += stride) {
        float4 a = ((const float4*)in)[2 * i];
        float4 b = ((const float4*)in)[2 * i + 1];
        float4 o0 = make_float4(tf32r(a.x), tf32r(b.x), tf32r(a.y), tf32r(b.y));
        float4 o1 = make_float4(tf32r(a.z), tf32r(b.z), tf32r(a.w), tf32r(b.w));
        ((float4*)out)[2 * i] = o0;
        ((float4*)out)[2 * i + 1] = o1;
    }
}

// transpose + tf32-round + k-permute: out[c][pi8(r)] = rna(in[r][c]); in is [R, Cc]
__global__ void transpose_tf32_kernel(const float* __restrict__ in, float* __restrict__ out,
                                      int R, int Cc)
{
    __shared__ float tile[32][33];
    int c0 = blockIdx.x * 32, r0 = blockIdx.y * 32;
    int tx = threadIdx.x, ty = threadIdx.y;
#pragma unroll
    for (int i = 0; i < 4; i++) {
        int r = r0 + ty + i * 8;
        tile[ty + i * 8][tx] = tf32r(in[(size_t)r * Cc + c0 + tx]);
    }
    __syncthreads();
#pragma unroll
    for (int i = 0; i < 4; i++) {
        int c = c0 + ty + i * 8;
        out[(size_t)c * R + r0 + pi8(tx)] = tile[tx][ty + i * 8];
    }
}

// ================= fused windowed attention (double softmax), fp32 =================
__global__ __launch_bounds__(64) void attn_kernel(
    const float* __restrict__ qkv, float* __restrict__ attnout)
{
    __shared__ float ks[64][64];
    __shared__ float vs[64][64];

    const int w = blockIdx.x, h = blockIdx.y, t = threadIdx.x;
    const float* base = qkv + (size_t)w * WIN * NQKV;

#pragma unroll
    for (int it = 0; it < 16; it++) {
        int f = t + 64 * it;
        int row = f >> 4;
        int c4 = (f & 15) << 2;
        *(float4*)&ks[row][c4] = *(const float4*)(base + (size_t)row * NQKV + 512 + h * HD + c4);
        *(float4*)&vs[row][c4] = *(const float4*)(base + (size_t)row * NQKV + 1024 + h * HD + c4);
    }

    ull q2[32];
    {
        const float* qrow = base + (size_t)t * NQKV + h * HD;
#pragma unroll
        for (int i = 0; i < 16; i++) {
            float4 v = *(const float4*)(qrow + 4 * i);
            q2[2 * i] = pack2(v.x, v.y);
            q2[2 * i + 1] = pack2(v.z, v.w);
        }
    }
    __syncthreads();

    float s[64];
#pragma unroll
    for (int j = 0; j < 64; j++) {
        ull acc = 0ULL;
#pragma unroll
        for (int d = 0; d < 32; d++) fma2(acc, q2[d], *(const ull*)&ks[j][2 * d]);
        float lo, hi; unpack2(acc, lo, hi);
        s[j] = (lo + hi) * 0.125f;
    }

    float m = -1e30f;
#pragma unroll
    for (int j = 0; j < 64; j++) if (j <= t) m = fmaxf(m, s[j]);
    float z = 0.f;
#pragma unroll
    for (int j = 0; j < 64; j++) {
        float e = (j <= t) ? __expf(s[j] - m) : 0.f;
        s[j] = e; z += e;
    }
    const float invz = 1.f / z;

    float z2 = 0.f;
#pragma unroll
    for (int j = 0; j < 64; j++) {
        float e2 = __expf(s[j] * invz);
        s[j] = e2; z2 += e2;
    }
    const float invz2 = 1.f / z2;

    ull o2[32];
#pragma unroll
    for (int d = 0; d < 32; d++) o2[d] = 0ULL;
#pragma unroll
    for (int j = 0; j < 64; j++) {
        ull pp = pack2(s[j] * invz2, s[j] * invz2);
#pragma unroll
        for (int d = 0; d < 32; d++) fma2(o2[d], pp, *(const ull*)&vs[j][2 * d]);
    }

    // unpack, tf32-round, k-permute within 8-groups, store (feeds GEMM2's A operand)
    float f[64];
#pragma unroll
    for (int d = 0; d < 32; d++) unpack2(o2[d], f[2 * d], f[2 * d + 1]);

    float* orow = attnout + ((size_t)(w * WIN + t)) * C_DIM + h * HD;
#pragma unroll
    for (int b = 0; b < 8; b++) {
        const float* fb = f + 8 * b;
        float4 w0 = make_float4(tf32r(fb[0]), tf32r(fb[4]), tf32r(fb[1]), tf32r(fb[5]));
        float4 w1 = make_float4(tf32r(fb[2]), tf32r(fb[6]), tf32r(fb[3]), tf32r(fb[7]));
        *(float4*)(orow + 8 * b) = w0;
        *(float4*)(orow + 8 * b + 4) = w1;
    }
}

// ================= launch =================
extern "C" void kernel_launch(void* const* d_in, const int* in_sizes, int n_in,
                              void* d_out, int out_size)
{
    const float* x     = (const float*)d_in[0];
    const float* Wqkv  = (const float*)d_in[1];
    const float* Wproj = (const float*)d_in[2];
    const float* bproj = (const float*)d_in[3];
    float* out = (float*)d_out;

    float *xr, *qkv, *attnout, *wqkvT, *wprojT;
    cudaGetSymbolAddress((void**)&xr, g_xr);
    cudaGetSymbolAddress((void**)&qkv, g_qkv);
    cudaGetSymbolAddress((void**)&attnout, g_attnout);
    cudaGetSymbolAddress((void**)&wqkvT, g_wqkvT);
    cudaGetSymbolAddress((void**)&wprojT, g_wprojT);

    cudaFuncSetAttribute(gemm_mma_kernel<false>, cudaFuncAttributeMaxDynamicSharedMemorySize, GEMM_SMEM);
    cudaFuncSetAttribute(gemm_mma_kernel<true>,  cudaFuncAttributeMaxDynamicSharedMemorySize, GEMM_SMEM);

    // prep: round+permute x, transpose+round+permute weights
    round_perm_kernel<<<2048, 256>>>(x, xr, (M_TOK * C_DIM) / 8);
    transpose_tf32_kernel<<<dim3(NQKV / 32, C_DIM / 32), dim3(32, 8)>>>(Wqkv, wqkvT, C_DIM, NQKV);
    transpose_tf32_kernel<<<dim3(C_DIM / 32, C_DIM / 32), dim3(32, 8)>>>(Wproj, wprojT, C_DIM, C_DIM);

    // 1) QKV projection: [65536,512] @ [512,1536]
    gemm_mma_kernel<false><<<dim3(NQKV / BN, M_TOK / BM), 256, GEMM_SMEM>>>(
        xr, wqkvT, nullptr, qkv, NQKV);

    // 2) windowed attention (double softmax)
    attn_kernel<<<dim3(NWIN, HEADS), 64>>>(qkv, attnout);

    // 3) output projection + bias: [65536,512] @ [512,512]
    gemm_mma_kernel<true><<<dim3(C_DIM / BN, M_TOK / BM), 256, GEMM_SMEM>>>(
        attnout, wprojT, bproj, out, C_DIM);
}